// round 2
// baseline (speedup 1.0000x reference)
#include <cuda_runtime.h>
#include <cstdint>

#define DIMC  1024
#define NH    16
#define HD    64
#define BATCH 4
#define SEQ   2048
#define MTOT  (BATCH*SEQ)   // 8192

// ---------------- scratch (device globals; no allocation allowed) ----------
__device__ float g_q[(size_t)BATCH*NH*SEQ*HD];     // [b*NH+h][t][d]
__device__ float g_k[(size_t)BATCH*NH*SEQ*HD];
__device__ float g_v[(size_t)BATCH*NH*SEQ*HD];
__device__ float g_attn[(size_t)MTOT*DIMC];        // [b*T+t][h*64+d]

// ---------------- helpers ---------------------------------------------------
__device__ __forceinline__ uint32_t f2tf(float f){
    uint32_t u; asm("cvt.rna.tf32.f32 %0, %1;" : "=r"(u) : "f"(f)); return u;
}

__device__ __forceinline__ void mma_tf32(float c[4], const uint32_t a[4], const uint32_t b[2]){
    asm volatile(
        "mma.sync.aligned.m16n8k8.row.col.f32.tf32.tf32.f32 "
        "{%0,%1,%2,%3}, {%4,%5,%6,%7}, {%8,%9}, {%0,%1,%2,%3};"
        : "+f"(c[0]), "+f"(c[1]), "+f"(c[2]), "+f"(c[3])
        : "r"(a[0]), "r"(a[1]), "r"(a[2]), "r"(a[3]), "r"(b[0]), "r"(b[1]));
}

// ---------------- GEMM: C[M,N] = A[M,K] @ W[N,K]^T (both K-major) -----------
// mode 0: A = g_attn, write Cout row-major   (output projection)
// mode 1/2/3: A = Ain (x), write g_q/g_k/g_v in [b*NH+h][t][d] layout
#define BM 128
#define BN 128
#define BK 32
#define LDA 36   // stride 36 == 4 (mod 32) -> conflict-free fragment reads

__global__ void __launch_bounds__(256, 1)
gemm_tf32(const float* __restrict__ Ain, const float* __restrict__ W,
          float* __restrict__ Cout, int mode)
{
    __shared__ uint32_t sA[BM*LDA];
    __shared__ uint32_t sB[BN*LDA];

    const float* A = (mode == 0) ? g_attn : Ain;
    const int K = DIMC;

    int tid  = threadIdx.x;
    int lane = tid & 31;
    int warp = tid >> 5;
    int wm = (warp >> 2) * 64;   // warp row offset within block tile
    int wn = (warp & 3) * 32;    // warp col offset
    int bm0 = blockIdx.y * BM;
    int bn0 = blockIdx.x * BN;

    float c[4][4][4];
    #pragma unroll
    for (int i = 0; i < 4; i++)
        #pragma unroll
        for (int j = 0; j < 4; j++)
            #pragma unroll
            for (int k = 0; k < 4; k++) c[i][j][k] = 0.f;

    float4 stA[4], stB[4];

    // prologue: tile 0 -> regs -> smem
    #pragma unroll
    for (int p = 0; p < 4; p++){
        int idx = tid + p*256;
        int r  = idx >> 3;
        int c4 = (idx & 7) << 2;
        stA[p] = *(const float4*)(A + (size_t)(bm0 + r)*K + c4);
        stB[p] = *(const float4*)(W + (size_t)(bn0 + r)*K + c4);
    }
    #pragma unroll
    for (int p = 0; p < 4; p++){
        int idx = tid + p*256;
        int r  = idx >> 3;
        int c4 = (idx & 7) << 2;
        uint32_t* da = &sA[r*LDA + c4];
        da[0]=f2tf(stA[p].x); da[1]=f2tf(stA[p].y); da[2]=f2tf(stA[p].z); da[3]=f2tf(stA[p].w);
        uint32_t* db = &sB[r*LDA + c4];
        db[0]=f2tf(stB[p].x); db[1]=f2tf(stB[p].y); db[2]=f2tf(stB[p].z); db[3]=f2tf(stB[p].w);
    }
    __syncthreads();

    const int NT = K / BK;   // 32
    for (int kt = 0; kt < NT; kt++){
        // prefetch next tile to registers (overlaps with mma below)
        if (kt + 1 < NT){
            int k0 = (kt + 1)*BK;
            #pragma unroll
            for (int p = 0; p < 4; p++){
                int idx = tid + p*256;
                int r  = idx >> 3;
                int c4 = (idx & 7) << 2;
                stA[p] = *(const float4*)(A + (size_t)(bm0 + r)*K + k0 + c4);
                stB[p] = *(const float4*)(W + (size_t)(bn0 + r)*K + k0 + c4);
            }
        }

        #pragma unroll
        for (int ks = 0; ks < 4; ks++){
            uint32_t af[4][4], bf[4][2];
            int col0 = ks*8 + (lane & 3);
            int row0 = wm + (lane >> 2);
            #pragma unroll
            for (int mt = 0; mt < 4; mt++){
                const uint32_t* p = &sA[(row0 + mt*16)*LDA + col0];
                af[mt][0] = p[0];
                af[mt][1] = p[8*LDA];
                af[mt][2] = p[4];
                af[mt][3] = p[8*LDA + 4];
            }
            #pragma unroll
            for (int nt = 0; nt < 4; nt++){
                const uint32_t* p = &sB[(wn + nt*8 + (lane >> 2))*LDA + col0];
                bf[nt][0] = p[0];
                bf[nt][1] = p[4];
            }
            #pragma unroll
            for (int mt = 0; mt < 4; mt++)
                #pragma unroll
                for (int nt = 0; nt < 4; nt++)
                    mma_tf32(c[mt][nt], af[mt], bf[nt]);
        }
        __syncthreads();
        if (kt + 1 < NT){
            #pragma unroll
            for (int p = 0; p < 4; p++){
                int idx = tid + p*256;
                int r  = idx >> 3;
                int c4 = (idx & 7) << 2;
                uint32_t* da = &sA[r*LDA + c4];
                da[0]=f2tf(stA[p].x); da[1]=f2tf(stA[p].y); da[2]=f2tf(stA[p].z); da[3]=f2tf(stA[p].w);
                uint32_t* db = &sB[r*LDA + c4];
                db[0]=f2tf(stB[p].x); db[1]=f2tf(stB[p].y); db[2]=f2tf(stB[p].z); db[3]=f2tf(stB[p].w);
            }
            __syncthreads();
        }
    }

    // epilogue
    #pragma unroll
    for (int mt = 0; mt < 4; mt++){
        #pragma unroll
        for (int nt = 0; nt < 4; nt++){
            int gr = bm0 + wm + mt*16 + (lane >> 2);
            int gc = bn0 + wn + nt*8 + ((lane & 3) << 1);
            float2 v0 = make_float2(c[mt][nt][0], c[mt][nt][1]);
            float2 v1 = make_float2(c[mt][nt][2], c[mt][nt][3]);
            if (mode == 0){
                *(float2*)(Cout + (size_t)gr*DIMC + gc)       = v0;
                *(float2*)(Cout + (size_t)(gr + 8)*DIMC + gc) = v1;
            } else {
                float* dst = (mode == 1) ? g_q : (mode == 2) ? g_k : g_v;
                int bb = gr >> 11;          // / SEQ
                int tt = gr & (SEQ - 1);
                int hh = gc >> 6;           // / HD
                int dd = gc & (HD - 1);
                size_t off = ((size_t)(bb*NH + hh)*SEQ + tt)*HD + dd;
                *(float2*)(dst + off)          = v0;   // row tt
                *(float2*)(dst + off + 8*HD)   = v1;   // row tt+8 (same b: tiles 128-aligned)
            }
        }
    }
}

// ---------------- causal flash attention (tf32 mma, fp32 softmax) -----------
#define QT 64
#define KTILE 32
#define LQ 68   // == 4 mod 32
#define LK 68
#define LV 72   // == 8 mod 32 (conflict-free for V B-fragments)
#define LP 36

__global__ void __launch_bounds__(128)
attn_tf32()
{
    __shared__ uint32_t sQ[QT*LQ];      // 17408 B
    __shared__ uint32_t sK[KTILE*LK];   //  8704 B
    __shared__ uint32_t sV[KTILE*LV];   //  9216 B
    __shared__ uint32_t sP[QT*LP];      //  9216 B   total 44544 B

    int tid  = threadIdx.x;
    int lane = tid & 31;
    int warp = tid >> 5;
    int bh = blockIdx.y;
    int q0 = blockIdx.x * QT;

    const float* Qg = g_q + (size_t)bh*SEQ*HD;
    const float* Kg = g_k + (size_t)bh*SEQ*HD;
    const float* Vg = g_v + (size_t)bh*SEQ*HD;

    // load Q tile (64x64 fp32) -> tf32 smem
    #pragma unroll
    for (int p = 0; p < 8; p++){
        int idx = tid + p*128;
        int r  = idx >> 4;
        int c4 = (idx & 15) << 2;
        float4 v = *(const float4*)(Qg + (size_t)(q0 + r)*HD + c4);
        uint32_t* d = &sQ[r*LQ + c4];
        d[0]=f2tf(v.x); d[1]=f2tf(v.y); d[2]=f2tf(v.z); d[3]=f2tf(v.w);
    }
    __syncthreads();

    // preload all Q fragments for this warp's 16 rows (8 k-steps over Dh=64)
    uint32_t qf[8][4];
    {
        int row0 = warp*16 + (lane >> 2);
        #pragma unroll
        for (int ks = 0; ks < 8; ks++){
            const uint32_t* p = &sQ[row0*LQ + ks*8 + (lane & 3)];
            qf[ks][0] = p[0];
            qf[ks][1] = p[8*LQ];
            qf[ks][2] = p[4];
            qf[ks][3] = p[8*LQ + 4];
        }
    }

    float o[8][4];
    #pragma unroll
    for (int i = 0; i < 8; i++)
        #pragma unroll
        for (int j = 0; j < 4; j++) o[i][j] = 0.f;
    float m0 = -1e30f, m1 = -1e30f, l0 = 0.f, l1 = 0.f;

    int nkt = (q0 + QT) / KTILE;   // causal: only tiles with keys <= q0+63
    for (int kt = 0; kt < nkt; kt++){
        __syncthreads();           // prior PV reads of sK/sV are done
        int kb = kt*KTILE;
        // load K,V tiles (32x64 each)
        #pragma unroll
        for (int p = 0; p < 4; p++){
            int idx = tid + p*128;
            int r  = idx >> 4;
            int c4 = (idx & 15) << 2;
            float4 kv = *(const float4*)(Kg + (size_t)(kb + r)*HD + c4);
            float4 vv = *(const float4*)(Vg + (size_t)(kb + r)*HD + c4);
            uint32_t* dk = &sK[r*LK + c4];
            dk[0]=f2tf(kv.x); dk[1]=f2tf(kv.y); dk[2]=f2tf(kv.z); dk[3]=f2tf(kv.w);
            uint32_t* dv = &sV[r*LV + c4];
            dv[0]=f2tf(vv.x); dv[1]=f2tf(vv.y); dv[2]=f2tf(vv.z); dv[3]=f2tf(vv.w);
        }
        __syncthreads();

        // S = Q @ K^T   (16 q-rows x 32 keys per warp)
        float s[4][4];
        #pragma unroll
        for (int i = 0; i < 4; i++)
            #pragma unroll
            for (int j = 0; j < 4; j++) s[i][j] = 0.f;
        #pragma unroll
        for (int ks = 0; ks < 8; ks++){
            #pragma unroll
            for (int nt = 0; nt < 4; nt++){
                uint32_t bf[2];
                const uint32_t* p = &sK[(nt*8 + (lane >> 2))*LK + ks*8 + (lane & 3)];
                bf[0] = p[0];
                bf[1] = p[4];
                mma_tf32(s[nt], qf[ks], bf);
            }
        }

        // scale + causal mask
        int qr0 = q0 + warp*16 + (lane >> 2);
        const float scale = 0.125f;  // 1/sqrt(64)
        #pragma unroll
        for (int nt = 0; nt < 4; nt++){
            int kc = kb + nt*8 + ((lane & 3) << 1);
            s[nt][0] = (kc     <= qr0    ) ? s[nt][0]*scale : -1e30f;
            s[nt][1] = (kc + 1 <= qr0    ) ? s[nt][1]*scale : -1e30f;
            s[nt][2] = (kc     <= qr0 + 8) ? s[nt][2]*scale : -1e30f;
            s[nt][3] = (kc + 1 <= qr0 + 8) ? s[nt][3]*scale : -1e30f;
        }

        // online softmax (rows lane/4 and lane/4+8; row lives in a lane-quad)
        float rm0 = -1e30f, rm1 = -1e30f;
        #pragma unroll
        for (int nt = 0; nt < 4; nt++){
            rm0 = fmaxf(rm0, fmaxf(s[nt][0], s[nt][1]));
            rm1 = fmaxf(rm1, fmaxf(s[nt][2], s[nt][3]));
        }
        rm0 = fmaxf(rm0, __shfl_xor_sync(0xffffffffu, rm0, 1));
        rm0 = fmaxf(rm0, __shfl_xor_sync(0xffffffffu, rm0, 2));
        rm1 = fmaxf(rm1, __shfl_xor_sync(0xffffffffu, rm1, 1));
        rm1 = fmaxf(rm1, __shfl_xor_sync(0xffffffffu, rm1, 2));

        float mn0 = fmaxf(m0, rm0), mn1 = fmaxf(m1, rm1);
        float a0 = __expf(m0 - mn0), a1 = __expf(m1 - mn1);
        float rs0 = 0.f, rs1 = 0.f;
        #pragma unroll
        for (int nt = 0; nt < 4; nt++){
            s[nt][0] = __expf(s[nt][0] - mn0);
            s[nt][1] = __expf(s[nt][1] - mn0);
            s[nt][2] = __expf(s[nt][2] - mn1);
            s[nt][3] = __expf(s[nt][3] - mn1);
            rs0 += s[nt][0] + s[nt][1];
            rs1 += s[nt][2] + s[nt][3];
        }
        rs0 += __shfl_xor_sync(0xffffffffu, rs0, 1);
        rs0 += __shfl_xor_sync(0xffffffffu, rs0, 2);
        rs1 += __shfl_xor_sync(0xffffffffu, rs1, 1);
        rs1 += __shfl_xor_sync(0xffffffffu, rs1, 2);
        l0 = l0*a0 + rs0;
        l1 = l1*a1 + rs1;
        m0 = mn0; m1 = mn1;
        #pragma unroll
        for (int nt = 0; nt < 8; nt++){
            o[nt][0] *= a0; o[nt][1] *= a0;
            o[nt][2] *= a1; o[nt][3] *= a1;
        }

        // P -> smem (tf32) to re-fragment as mma A operand
        int pr = warp*16 + (lane >> 2);
        #pragma unroll
        for (int nt = 0; nt < 4; nt++){
            uint32_t* p = &sP[pr*LP + nt*8 + ((lane & 3) << 1)];
            p[0]        = f2tf(s[nt][0]);
            p[1]        = f2tf(s[nt][1]);
            p[8*LP]     = f2tf(s[nt][2]);
            p[8*LP + 1] = f2tf(s[nt][3]);
        }
        __syncwarp();   // each warp only touches its own 16 rows of sP

        // O += P @ V
        #pragma unroll
        for (int ks = 0; ks < 4; ks++){
            uint32_t af[4];
            const uint32_t* pa = &sP[pr*LP + ks*8 + (lane & 3)];
            af[0] = pa[0];
            af[1] = pa[8*LP];
            af[2] = pa[4];
            af[3] = pa[8*LP + 4];
            #pragma unroll
            for (int nt = 0; nt < 8; nt++){
                uint32_t bf[2];
                const uint32_t* pb = &sV[(ks*8 + (lane & 3))*LV + nt*8 + (lane >> 2)];
                bf[0] = pb[0];
                bf[1] = pb[4*LV];
                mma_tf32(o[nt], af, bf);
            }
        }
        __syncwarp();   // WAR: sP reads done before next iter rewrites
    }

    // epilogue: O/l -> g_attn [b*T+t][h*64+d]
    float il0 = 1.0f / l0, il1 = 1.0f / l1;
    int b = bh >> 4, h = bh & 15;
    int t0 = q0 + warp*16 + (lane >> 2);
    #pragma unroll
    for (int nt = 0; nt < 8; nt++){
        int d = nt*8 + ((lane & 3) << 1);
        size_t base = ((size_t)(b*SEQ + t0))*DIMC + h*HD + d;
        *(float2*)(g_attn + base)                 = make_float2(o[nt][0]*il0, o[nt][1]*il0);
        *(float2*)(g_attn + base + (size_t)8*DIMC) = make_float2(o[nt][2]*il1, o[nt][3]*il1);
    }
}

// ---------------- launch ----------------------------------------------------
extern "C" void kernel_launch(void* const* d_in, const int* in_sizes, int n_in,
                              void* d_out, int out_size)
{
    const float* x  = (const float*)d_in[0];
    const float* wq = (const float*)d_in[1];
    const float* wk = (const float*)d_in[2];
    const float* wv = (const float*)d_in[3];
    const float* wo = (const float*)d_in[4];
    float* out = (float*)d_out;

    dim3 gg(DIMC/BN, MTOT/BM, 1);   // (8, 64)
    gemm_tf32<<<gg, 256>>>(x, wq, nullptr, 1);   // -> g_q
    gemm_tf32<<<gg, 256>>>(x, wk, nullptr, 2);   // -> g_k
    gemm_tf32<<<gg, 256>>>(x, wv, nullptr, 3);   // -> g_v
    attn_tf32<<<dim3(SEQ/QT, BATCH*NH), 128>>>();
    gemm_tf32<<<gg, 256>>>(nullptr, wo, out, 0); // g_attn @ wo^T -> out
}